// round 8
// baseline (speedup 1.0000x reference)
#include <cuda_runtime.h>

// WeightedProcrustes: B=8192 batches, N=512 points.
// R5/R7: one batch per warp (grid 1024), explicit next-iteration prefetch so
// each warp keeps 7 float4 loads in flight while accumulating -> saturate DRAM.
// (R6 bench was an infra failure; this is a clean re-bench of the R5 design.)

#define PB 8192
#define PN 512

constexpr int BPC = 8;       // batches per CTA = warps per CTA
constexpr int THREADS = 256; // 8 warps, 1 batch per warp

__global__ __launch_bounds__(THREADS, 2) void wproc_kernel(
    const float* __restrict__ src, const float* __restrict__ tgt,
    const float* __restrict__ wgt, float* __restrict__ out)
{
    __shared__ float red[BPC][17];  // 17-stride: conflict-free column reads

    const int lane = threadIdx.x & 31;
    const int warp = threadIdx.x >> 5;
    const int ctaBase = blockIdx.x * BPC;

    // ---------------- Phase 1: one batch per warp, pipelined loads ----------------
    {
        const int b = ctaBase + warp;
        const float4* s4 = reinterpret_cast<const float4*>(src) + (size_t)b * (PN * 3 / 4);
        const float4* t4 = reinterpret_cast<const float4*>(tgt) + (size_t)b * (PN * 3 / 4);
        const float4* w4 = reinterpret_cast<const float4*>(wgt) + (size_t)b * (PN / 4);

        float S = 0.f, sx = 0.f, sy = 0.f, sz = 0.f, tx = 0.f, ty = 0.f, tz = 0.f;
        float M00 = 0.f, M01 = 0.f, M02 = 0.f;
        float M10 = 0.f, M11 = 0.f, M12 = 0.f;
        float M20 = 0.f, M21 = 0.f, M22 = 0.f;

        auto acc = [&](float w, float ax, float ay, float az,
                       float bx, float by, float bz) {
            w = fmaxf(w, 0.0f);  // threshold at 0.0
            S += w;
            float wx = w * ax, wy = w * ay, wz = w * az;
            sx += wx; sy += wy; sz += wz;
            tx = fmaf(w, bx, tx); ty = fmaf(w, by, ty); tz = fmaf(w, bz, tz);
            M00 = fmaf(wx, bx, M00); M01 = fmaf(wx, by, M01); M02 = fmaf(wx, bz, M02);
            M10 = fmaf(wy, bx, M10); M11 = fmaf(wy, by, M11); M12 = fmaf(wy, bz, M12);
            M20 = fmaf(wz, bx, M20); M21 = fmaf(wz, by, M21); M22 = fmaf(wz, bz, M22);
        };

        // prologue: load group 0
        int g = lane;
        float4 sa = s4[3 * g + 0];
        float4 sb = s4[3 * g + 1];
        float4 sc = s4[3 * g + 2];
        float4 ta = t4[3 * g + 0];
        float4 tb = t4[3 * g + 1];
        float4 tc = t4[3 * g + 2];
        float4 wv = w4[g];

        #pragma unroll
        for (int k = 0; k < 4; k++) {
            // prefetch next group while this one is consumed
            float4 nsa, nsb, nsc, nta, ntb, ntc, nwv;
            if (k < 3) {
                const int gn = g + 32;
                nsa = s4[3 * gn + 0];
                nsb = s4[3 * gn + 1];
                nsc = s4[3 * gn + 2];
                nta = t4[3 * gn + 0];
                ntb = t4[3 * gn + 1];
                ntc = t4[3 * gn + 2];
                nwv = w4[gn];
            }
            acc(wv.x, sa.x, sa.y, sa.z, ta.x, ta.y, ta.z);
            acc(wv.y, sa.w, sb.x, sb.y, ta.w, tb.x, tb.y);
            acc(wv.z, sb.z, sb.w, sc.x, tb.z, tb.w, tc.x);
            acc(wv.w, sc.y, sc.z, sc.w, tc.y, tc.z, tc.w);
            if (k < 3) {
                sa = nsa; sb = nsb; sc = nsc;
                ta = nta; tb = ntb; tc = ntc;
                wv = nwv;
                g += 32;
            }
        }

        float v[16] = {S, sx, sy, sz, tx, ty, tz,
                       M00, M01, M02, M10, M11, M12, M20, M21, M22};
        #pragma unroll
        for (int o = 16; o > 0; o >>= 1) {
            #pragma unroll
            for (int i = 0; i < 16; i++)
                v[i] += __shfl_xor_sync(0xffffffffu, v[i], o);
        }
        if (lane == 0) {
            #pragma unroll
            for (int i = 0; i < 16; i++) red[warp][i] = v[i];
        }
    }

    __syncthreads();

    // ---------------- Phase 2: one batch per lane (threads 0..BPC-1) ----------------
    if (threadIdx.x < BPC) {
        const int bl = threadIdx.x;
        const int b  = ctaBase + bl;

        float S  = red[bl][0];
        float sx = red[bl][1], sy = red[bl][2], sz = red[bl][3];
        float tx = red[bl][4], ty = red[bl][5], tz = red[bl][6];
        float M00 = red[bl][7],  M01 = red[bl][8],  M02 = red[bl][9];
        float M10 = red[bl][10], M11 = red[bl][11], M12 = red[bl][12];
        float M20 = red[bl][13], M21 = red[bl][14], M22 = red[bl][15];

        const float invD = __fdividef(1.0f, S + 1e-5f);
        const float kc   = (2.0f - S * invD) * invD;  // (2-W)/D

        // H = M - kc * sx * tx^T   (scale of H is irrelevant for the eigenvector)
        float H00 = fmaf(-kc * sx, tx, M00), H01 = fmaf(-kc * sx, ty, M01), H02 = fmaf(-kc * sx, tz, M02);
        float H10 = fmaf(-kc * sy, tx, M10), H11 = fmaf(-kc * sy, ty, M11), H12 = fmaf(-kc * sy, tz, M12);
        float H20 = fmaf(-kc * sz, tx, M20), H21 = fmaf(-kc * sz, ty, M21), H22 = fmaf(-kc * sz, tz, M22);

        // Horn's 4x4 symmetric matrix
        float A[4][4], V[4][4];
        A[0][0] = H00 + H11 + H22;
        A[0][1] = H12 - H21;  A[0][2] = H20 - H02;  A[0][3] = H01 - H10;
        A[1][1] = H00 - H11 - H22;
        A[1][2] = H01 + H10;  A[1][3] = H20 + H02;
        A[2][2] = -H00 + H11 - H22;
        A[2][3] = H12 + H21;
        A[3][3] = -H00 - H11 + H22;
        A[1][0] = A[0][1]; A[2][0] = A[0][2]; A[3][0] = A[0][3];
        A[2][1] = A[1][2]; A[3][1] = A[1][3]; A[3][2] = A[2][3];
        #pragma unroll
        for (int i = 0; i < 4; i++)
            #pragma unroll
            for (int j = 0; j < 4; j++)
                V[i][j] = (i == j) ? 1.0f : 0.0f;

        // Cyclic Jacobi, 6 sweeps
        #pragma unroll
        for (int sweep = 0; sweep < 6; sweep++) {
            #pragma unroll
            for (int pi = 0; pi < 6; pi++) {
                const int Pidx[6] = {0, 0, 0, 1, 1, 2};
                const int Qidx[6] = {1, 2, 3, 2, 3, 3};
                const int p = Pidx[pi], q = Qidx[pi];
                float apq = A[p][q];
                float c, s, t;
                if (fabsf(apq) > 1e-25f) {
                    float theta = (A[q][q] - A[p][p]) * 0.5f / apq;
                    t = copysignf(1.0f, theta) /
                        (fabsf(theta) + sqrtf(fmaf(theta, theta, 1.0f)));
                    c = rsqrtf(fmaf(t, t, 1.0f));
                    s = t * c;
                } else {
                    c = 1.0f; s = 0.0f; t = 0.0f;
                }
                A[p][p] = fmaf(-t, apq, A[p][p]);
                A[q][q] = fmaf( t, apq, A[q][q]);
                A[p][q] = 0.0f; A[q][p] = 0.0f;
                #pragma unroll
                for (int r = 0; r < 4; r++) {
                    if (r != p && r != q) {
                        float arp = A[r][p], arq = A[r][q];
                        A[r][p] = A[p][r] = fmaf(c, arp, -s * arq);
                        A[r][q] = A[q][r] = fmaf(s, arp,  c * arq);
                    }
                    float vrp = V[r][p], vrq = V[r][q];
                    V[r][p] = fmaf(c, vrp, -s * vrq);
                    V[r][q] = fmaf(s, vrp,  c * vrq);
                }
            }
        }

        // pick eigenvector of max eigenvalue
        float dm = A[0][0];
        float q0 = V[0][0], qx = V[1][0], qy = V[2][0], qz = V[3][0];
        if (A[1][1] > dm) { dm = A[1][1]; q0 = V[0][1]; qx = V[1][1]; qy = V[2][1]; qz = V[3][1]; }
        if (A[2][2] > dm) { dm = A[2][2]; q0 = V[0][2]; qx = V[1][2]; qy = V[2][2]; qz = V[3][2]; }
        if (A[3][3] > dm) { dm = A[3][3]; q0 = V[0][3]; qx = V[1][3]; qy = V[2][3]; qz = V[3][3]; }

        float rn = rsqrtf(q0 * q0 + qx * qx + qy * qy + qz * qz);
        q0 *= rn; qx *= rn; qy *= rn; qz *= rn;

        // quaternion -> rotation matrix (maps src -> tgt)
        float xx = qx * qx, yy = qy * qy, zz = qz * qz;
        float xy = qx * qy, xz = qx * qz, yz = qy * qz;
        float wxq = q0 * qx, wyq = q0 * qy, wzq = q0 * qz;
        float R00 = 1.0f - 2.0f * (yy + zz), R01 = 2.0f * (xy - wzq), R02 = 2.0f * (xz + wyq);
        float R10 = 2.0f * (xy + wzq), R11 = 1.0f - 2.0f * (xx + zz), R12 = 2.0f * (yz - wxq);
        float R20 = 2.0f * (xz - wyq), R21 = 2.0f * (yz + wxq), R22 = 1.0f - 2.0f * (xx + yy);

        // centroids and translation: t = tgt_c - R * src_c
        float cxs = sx * invD, cys = sy * invD, czs = sz * invD;
        float cxt = tx * invD, cyt = ty * invD, czt = tz * invD;
        float t0 = cxt - (R00 * cxs + R01 * cys + R02 * czs);
        float t1 = cyt - (R10 * cxs + R11 * cys + R12 * czs);
        float t2 = czt - (R20 * cxs + R21 * cys + R22 * czs);

        float* Ro = out + (size_t)b * 9;
        Ro[0] = R00; Ro[1] = R01; Ro[2] = R02;
        Ro[3] = R10; Ro[4] = R11; Ro[5] = R12;
        Ro[6] = R20; Ro[7] = R21; Ro[8] = R22;
        float* To = out + (size_t)PB * 9 + (size_t)b * 3;
        To[0] = t0; To[1] = t1; To[2] = t2;
    }
}

extern "C" void kernel_launch(void* const* d_in, const int* in_sizes, int n_in,
                              void* d_out, int out_size) {
    const float* src = (const float*)d_in[0];
    const float* tgt = (const float*)d_in[1];
    const float* wgt = (const float*)d_in[2];
    float* out = (float*)d_out;
    wproc_kernel<<<PB / BPC, THREADS>>>(src, tgt, wgt, out);
}

// round 9
// speedup vs baseline: 1.2806x; 1.2806x over previous
#include <cuda_runtime.h>

// WeightedProcrustes: B=8192 batches, N=512 points.
// R9: one batch per warp, small CTAs (128 thr, BPC=4, grid=2048), NO explicit
// prefetch (keeps regs ~64 so 8 CTAs/SM fit). Occupancy, not per-warp
// pipelining, supplies the outstanding-load parallelism.

#define PB 8192
#define PN 512

constexpr int BPC = 4;       // batches per CTA = warps per CTA
constexpr int THREADS = 128; // 4 warps, 1 batch per warp

__global__ __launch_bounds__(THREADS) void wproc_kernel(
    const float* __restrict__ src, const float* __restrict__ tgt,
    const float* __restrict__ wgt, float* __restrict__ out)
{
    __shared__ float red[BPC][17];  // 17-stride: conflict-free column reads

    const int lane = threadIdx.x & 31;
    const int warp = threadIdx.x >> 5;
    const int ctaBase = blockIdx.x * BPC;

    // ---------------- Phase 1: one batch per warp ----------------
    {
        const int b = ctaBase + warp;
        const float4* s4 = reinterpret_cast<const float4*>(src) + (size_t)b * (PN * 3 / 4);
        const float4* t4 = reinterpret_cast<const float4*>(tgt) + (size_t)b * (PN * 3 / 4);
        const float4* w4 = reinterpret_cast<const float4*>(wgt) + (size_t)b * (PN / 4);

        float S = 0.f, sx = 0.f, sy = 0.f, sz = 0.f, tx = 0.f, ty = 0.f, tz = 0.f;
        float M00 = 0.f, M01 = 0.f, M02 = 0.f;
        float M10 = 0.f, M11 = 0.f, M12 = 0.f;
        float M20 = 0.f, M21 = 0.f, M22 = 0.f;

        auto acc = [&](float w, float ax, float ay, float az,
                       float bx, float by, float bz) {
            w = fmaxf(w, 0.0f);  // threshold at 0.0
            S += w;
            float wx = w * ax, wy = w * ay, wz = w * az;
            sx += wx; sy += wy; sz += wz;
            tx = fmaf(w, bx, tx); ty = fmaf(w, by, ty); tz = fmaf(w, bz, tz);
            M00 = fmaf(wx, bx, M00); M01 = fmaf(wx, by, M01); M02 = fmaf(wx, bz, M02);
            M10 = fmaf(wy, bx, M10); M11 = fmaf(wy, by, M11); M12 = fmaf(wy, bz, M12);
            M20 = fmaf(wz, bx, M20); M21 = fmaf(wz, by, M21); M22 = fmaf(wz, bz, M22);
        };

        #pragma unroll
        for (int k = 0; k < 4; k++) {
            const int g = k * 32 + lane;           // group of 4 points
            float4 sa = s4[3 * g + 0];
            float4 sb = s4[3 * g + 1];
            float4 sc = s4[3 * g + 2];
            float4 ta = t4[3 * g + 0];
            float4 tb = t4[3 * g + 1];
            float4 tc = t4[3 * g + 2];
            float4 wv = w4[g];
            acc(wv.x, sa.x, sa.y, sa.z, ta.x, ta.y, ta.z);
            acc(wv.y, sa.w, sb.x, sb.y, ta.w, tb.x, tb.y);
            acc(wv.z, sb.z, sb.w, sc.x, tb.z, tb.w, tc.x);
            acc(wv.w, sc.y, sc.z, sc.w, tc.y, tc.z, tc.w);
        }

        float v[16] = {S, sx, sy, sz, tx, ty, tz,
                       M00, M01, M02, M10, M11, M12, M20, M21, M22};
        #pragma unroll
        for (int o = 16; o > 0; o >>= 1) {
            #pragma unroll
            for (int i = 0; i < 16; i++)
                v[i] += __shfl_xor_sync(0xffffffffu, v[i], o);
        }
        if (lane == 0) {
            #pragma unroll
            for (int i = 0; i < 16; i++) red[warp][i] = v[i];
        }
    }

    __syncthreads();

    // ---------------- Phase 2: one batch per lane (threads 0..BPC-1) ----------------
    if (threadIdx.x < BPC) {
        const int bl = threadIdx.x;
        const int b  = ctaBase + bl;

        float S  = red[bl][0];
        float sx = red[bl][1], sy = red[bl][2], sz = red[bl][3];
        float tx = red[bl][4], ty = red[bl][5], tz = red[bl][6];
        float M00 = red[bl][7],  M01 = red[bl][8],  M02 = red[bl][9];
        float M10 = red[bl][10], M11 = red[bl][11], M12 = red[bl][12];
        float M20 = red[bl][13], M21 = red[bl][14], M22 = red[bl][15];

        const float invD = __fdividef(1.0f, S + 1e-5f);
        const float kc   = (2.0f - S * invD) * invD;  // (2-W)/D

        // H = M - kc * sx * tx^T   (scale of H is irrelevant for the eigenvector)
        float H00 = fmaf(-kc * sx, tx, M00), H01 = fmaf(-kc * sx, ty, M01), H02 = fmaf(-kc * sx, tz, M02);
        float H10 = fmaf(-kc * sy, tx, M10), H11 = fmaf(-kc * sy, ty, M11), H12 = fmaf(-kc * sy, tz, M12);
        float H20 = fmaf(-kc * sz, tx, M20), H21 = fmaf(-kc * sz, ty, M21), H22 = fmaf(-kc * sz, tz, M22);

        // Horn's 4x4 symmetric matrix
        float A[4][4], V[4][4];
        A[0][0] = H00 + H11 + H22;
        A[0][1] = H12 - H21;  A[0][2] = H20 - H02;  A[0][3] = H01 - H10;
        A[1][1] = H00 - H11 - H22;
        A[1][2] = H01 + H10;  A[1][3] = H20 + H02;
        A[2][2] = -H00 + H11 - H22;
        A[2][3] = H12 + H21;
        A[3][3] = -H00 - H11 + H22;
        A[1][0] = A[0][1]; A[2][0] = A[0][2]; A[3][0] = A[0][3];
        A[2][1] = A[1][2]; A[3][1] = A[1][3]; A[3][2] = A[2][3];
        #pragma unroll
        for (int i = 0; i < 4; i++)
            #pragma unroll
            for (int j = 0; j < 4; j++)
                V[i][j] = (i == j) ? 1.0f : 0.0f;

        // Cyclic Jacobi, 6 sweeps
        #pragma unroll
        for (int sweep = 0; sweep < 6; sweep++) {
            #pragma unroll
            for (int pi = 0; pi < 6; pi++) {
                const int Pidx[6] = {0, 0, 0, 1, 1, 2};
                const int Qidx[6] = {1, 2, 3, 2, 3, 3};
                const int p = Pidx[pi], q = Qidx[pi];
                float apq = A[p][q];
                float c, s, t;
                if (fabsf(apq) > 1e-25f) {
                    float theta = (A[q][q] - A[p][p]) * 0.5f / apq;
                    t = copysignf(1.0f, theta) /
                        (fabsf(theta) + sqrtf(fmaf(theta, theta, 1.0f)));
                    c = rsqrtf(fmaf(t, t, 1.0f));
                    s = t * c;
                } else {
                    c = 1.0f; s = 0.0f; t = 0.0f;
                }
                A[p][p] = fmaf(-t, apq, A[p][p]);
                A[q][q] = fmaf( t, apq, A[q][q]);
                A[p][q] = 0.0f; A[q][p] = 0.0f;
                #pragma unroll
                for (int r = 0; r < 4; r++) {
                    if (r != p && r != q) {
                        float arp = A[r][p], arq = A[r][q];
                        A[r][p] = A[p][r] = fmaf(c, arp, -s * arq);
                        A[r][q] = A[q][r] = fmaf(s, arp,  c * arq);
                    }
                    float vrp = V[r][p], vrq = V[r][q];
                    V[r][p] = fmaf(c, vrp, -s * vrq);
                    V[r][q] = fmaf(s, vrp,  c * vrq);
                }
            }
        }

        // pick eigenvector of max eigenvalue
        float dm = A[0][0];
        float q0 = V[0][0], qx = V[1][0], qy = V[2][0], qz = V[3][0];
        if (A[1][1] > dm) { dm = A[1][1]; q0 = V[0][1]; qx = V[1][1]; qy = V[2][1]; qz = V[3][1]; }
        if (A[2][2] > dm) { dm = A[2][2]; q0 = V[0][2]; qx = V[1][2]; qy = V[2][2]; qz = V[3][2]; }
        if (A[3][3] > dm) { dm = A[3][3]; q0 = V[0][3]; qx = V[1][3]; qy = V[2][3]; qz = V[3][3]; }

        float rn = rsqrtf(q0 * q0 + qx * qx + qy * qy + qz * qz);
        q0 *= rn; qx *= rn; qy *= rn; qz *= rn;

        // quaternion -> rotation matrix (maps src -> tgt)
        float xx = qx * qx, yy = qy * qy, zz = qz * qz;
        float xy = qx * qy, xz = qx * qz, yz = qy * qz;
        float wxq = q0 * qx, wyq = q0 * qy, wzq = q0 * qz;
        float R00 = 1.0f - 2.0f * (yy + zz), R01 = 2.0f * (xy - wzq), R02 = 2.0f * (xz + wyq);
        float R10 = 2.0f * (xy + wzq), R11 = 1.0f - 2.0f * (xx + zz), R12 = 2.0f * (yz - wxq);
        float R20 = 2.0f * (xz - wyq), R21 = 2.0f * (yz + wxq), R22 = 1.0f - 2.0f * (xx + yy);

        // centroids and translation: t = tgt_c - R * src_c
        float cxs = sx * invD, cys = sy * invD, czs = sz * invD;
        float cxt = tx * invD, cyt = ty * invD, czt = tz * invD;
        float t0 = cxt - (R00 * cxs + R01 * cys + R02 * czs);
        float t1 = cyt - (R10 * cxs + R11 * cys + R12 * czs);
        float t2 = czt - (R20 * cxs + R21 * cys + R22 * czs);

        float* Ro = out + (size_t)b * 9;
        Ro[0] = R00; Ro[1] = R01; Ro[2] = R02;
        Ro[3] = R10; Ro[4] = R11; Ro[5] = R12;
        Ro[6] = R20; Ro[7] = R21; Ro[8] = R22;
        float* To = out + (size_t)PB * 9 + (size_t)b * 3;
        To[0] = t0; To[1] = t1; To[2] = t2;
    }
}

extern "C" void kernel_launch(void* const* d_in, const int* in_sizes, int n_in,
                              void* d_out, int out_size) {
    const float* src = (const float*)d_in[0];
    const float* tgt = (const float*)d_in[1];
    const float* wgt = (const float*)d_in[2];
    float* out = (float*)d_out;
    wproc_kernel<<<PB / BPC, THREADS>>>(src, tgt, wgt, out);
}

// round 10
// speedup vs baseline: 1.4590x; 1.1393x over previous
#include <cuda_runtime.h>

// WeightedProcrustes: B=8192 batches, N=512 points.
// R10: two-kernel split.
//   K1: pure streaming reduction (one batch per warp, no tail, no smem) ->
//       16 sufficient statistics per batch into __device__ scratch.
//   K2: 8192 independent Horn-quaternion solves, one per THREAD (all Jacobi
//       tails run in parallel instead of serializing inside reduction CTAs).

#define PB 8192
#define PN 512

constexpr int BPC = 4;        // batches per CTA in K1 (= warps per CTA)
constexpr int K1_THREADS = 128;
constexpr int K2_THREADS = 128;

// scratch[i][b]: statistic i of batch b (transposed for coalesced K2 reads)
__device__ float g_scratch[16][PB];

// ---------------------------------------------------------------------------
// Kernel 1: reduction only
// ---------------------------------------------------------------------------
__global__ __launch_bounds__(K1_THREADS) void wproc_reduce(
    const float* __restrict__ src, const float* __restrict__ tgt,
    const float* __restrict__ wgt)
{
    const int lane = threadIdx.x & 31;
    const int warp = threadIdx.x >> 5;
    const int b = blockIdx.x * BPC + warp;

    const float4* s4 = reinterpret_cast<const float4*>(src) + (size_t)b * (PN * 3 / 4);
    const float4* t4 = reinterpret_cast<const float4*>(tgt) + (size_t)b * (PN * 3 / 4);
    const float4* w4 = reinterpret_cast<const float4*>(wgt) + (size_t)b * (PN / 4);

    float S = 0.f, sx = 0.f, sy = 0.f, sz = 0.f, tx = 0.f, ty = 0.f, tz = 0.f;
    float M00 = 0.f, M01 = 0.f, M02 = 0.f;
    float M10 = 0.f, M11 = 0.f, M12 = 0.f;
    float M20 = 0.f, M21 = 0.f, M22 = 0.f;

    auto acc = [&](float w, float ax, float ay, float az,
                   float bx, float by, float bz) {
        w = fmaxf(w, 0.0f);  // threshold at 0.0
        S += w;
        float wx = w * ax, wy = w * ay, wz = w * az;
        sx += wx; sy += wy; sz += wz;
        tx = fmaf(w, bx, tx); ty = fmaf(w, by, ty); tz = fmaf(w, bz, tz);
        M00 = fmaf(wx, bx, M00); M01 = fmaf(wx, by, M01); M02 = fmaf(wx, bz, M02);
        M10 = fmaf(wy, bx, M10); M11 = fmaf(wy, by, M11); M12 = fmaf(wy, bz, M12);
        M20 = fmaf(wz, bx, M20); M21 = fmaf(wz, by, M21); M22 = fmaf(wz, bz, M22);
    };

    #pragma unroll
    for (int k = 0; k < 4; k++) {
        const int g = k * 32 + lane;           // group of 4 points
        float4 sa = s4[3 * g + 0];
        float4 sb = s4[3 * g + 1];
        float4 sc = s4[3 * g + 2];
        float4 ta = t4[3 * g + 0];
        float4 tb = t4[3 * g + 1];
        float4 tc = t4[3 * g + 2];
        float4 wv = w4[g];
        acc(wv.x, sa.x, sa.y, sa.z, ta.x, ta.y, ta.z);
        acc(wv.y, sa.w, sb.x, sb.y, ta.w, tb.x, tb.y);
        acc(wv.z, sb.z, sb.w, sc.x, tb.z, tb.w, tc.x);
        acc(wv.w, sc.y, sc.z, sc.w, tc.y, tc.z, tc.w);
    }

    float v[16] = {S, sx, sy, sz, tx, ty, tz,
                   M00, M01, M02, M10, M11, M12, M20, M21, M22};
    #pragma unroll
    for (int o = 16; o > 0; o >>= 1) {
        #pragma unroll
        for (int i = 0; i < 16; i++)
            v[i] += __shfl_xor_sync(0xffffffffu, v[i], o);
    }
    if (lane == 0) {
        #pragma unroll
        for (int i = 0; i < 16; i++) g_scratch[i][b] = v[i];
    }
}

// ---------------------------------------------------------------------------
// Kernel 2: one batch per thread — Horn quaternion via 4x4 Jacobi
// ---------------------------------------------------------------------------
__global__ __launch_bounds__(K2_THREADS) void wproc_solve(float* __restrict__ out)
{
    const int b = blockIdx.x * K2_THREADS + threadIdx.x;

    const float S  = g_scratch[0][b];
    const float sx = g_scratch[1][b], sy = g_scratch[2][b], sz = g_scratch[3][b];
    const float tx = g_scratch[4][b], ty = g_scratch[5][b], tz = g_scratch[6][b];
    const float M00 = g_scratch[7][b],  M01 = g_scratch[8][b],  M02 = g_scratch[9][b];
    const float M10 = g_scratch[10][b], M11 = g_scratch[11][b], M12 = g_scratch[12][b];
    const float M20 = g_scratch[13][b], M21 = g_scratch[14][b], M22 = g_scratch[15][b];

    const float invD = __fdividef(1.0f, S + 1e-5f);
    const float kc   = (2.0f - S * invD) * invD;  // (2-W)/D

    // H = M - kc * sx * tx^T   (scale of H is irrelevant for the eigenvector)
    float H00 = fmaf(-kc * sx, tx, M00), H01 = fmaf(-kc * sx, ty, M01), H02 = fmaf(-kc * sx, tz, M02);
    float H10 = fmaf(-kc * sy, tx, M10), H11 = fmaf(-kc * sy, ty, M11), H12 = fmaf(-kc * sy, tz, M12);
    float H20 = fmaf(-kc * sz, tx, M20), H21 = fmaf(-kc * sz, ty, M21), H22 = fmaf(-kc * sz, tz, M22);

    // Horn's 4x4 symmetric matrix
    float A[4][4], V[4][4];
    A[0][0] = H00 + H11 + H22;
    A[0][1] = H12 - H21;  A[0][2] = H20 - H02;  A[0][3] = H01 - H10;
    A[1][1] = H00 - H11 - H22;
    A[1][2] = H01 + H10;  A[1][3] = H20 + H02;
    A[2][2] = -H00 + H11 - H22;
    A[2][3] = H12 + H21;
    A[3][3] = -H00 - H11 + H22;
    A[1][0] = A[0][1]; A[2][0] = A[0][2]; A[3][0] = A[0][3];
    A[2][1] = A[1][2]; A[3][1] = A[1][3]; A[3][2] = A[2][3];
    #pragma unroll
    for (int i = 0; i < 4; i++)
        #pragma unroll
        for (int j = 0; j < 4; j++)
            V[i][j] = (i == j) ? 1.0f : 0.0f;

    // Cyclic Jacobi, 6 sweeps
    #pragma unroll
    for (int sweep = 0; sweep < 6; sweep++) {
        #pragma unroll
        for (int pi = 0; pi < 6; pi++) {
            const int Pidx[6] = {0, 0, 0, 1, 1, 2};
            const int Qidx[6] = {1, 2, 3, 2, 3, 3};
            const int p = Pidx[pi], q = Qidx[pi];
            float apq = A[p][q];
            float c, s, t;
            if (fabsf(apq) > 1e-25f) {
                float theta = (A[q][q] - A[p][p]) * 0.5f / apq;
                t = copysignf(1.0f, theta) /
                    (fabsf(theta) + sqrtf(fmaf(theta, theta, 1.0f)));
                c = rsqrtf(fmaf(t, t, 1.0f));
                s = t * c;
            } else {
                c = 1.0f; s = 0.0f; t = 0.0f;
            }
            A[p][p] = fmaf(-t, apq, A[p][p]);
            A[q][q] = fmaf( t, apq, A[q][q]);
            A[p][q] = 0.0f; A[q][p] = 0.0f;
            #pragma unroll
            for (int r = 0; r < 4; r++) {
                if (r != p && r != q) {
                    float arp = A[r][p], arq = A[r][q];
                    A[r][p] = A[p][r] = fmaf(c, arp, -s * arq);
                    A[r][q] = A[q][r] = fmaf(s, arp,  c * arq);
                }
                float vrp = V[r][p], vrq = V[r][q];
                V[r][p] = fmaf(c, vrp, -s * vrq);
                V[r][q] = fmaf(s, vrp,  c * vrq);
            }
        }
    }

    // pick eigenvector of max eigenvalue
    float dm = A[0][0];
    float q0 = V[0][0], qx = V[1][0], qy = V[2][0], qz = V[3][0];
    if (A[1][1] > dm) { dm = A[1][1]; q0 = V[0][1]; qx = V[1][1]; qy = V[2][1]; qz = V[3][1]; }
    if (A[2][2] > dm) { dm = A[2][2]; q0 = V[0][2]; qx = V[1][2]; qy = V[2][2]; qz = V[3][2]; }
    if (A[3][3] > dm) { dm = A[3][3]; q0 = V[0][3]; qx = V[1][3]; qy = V[2][3]; qz = V[3][3]; }

    float rn = rsqrtf(q0 * q0 + qx * qx + qy * qy + qz * qz);
    q0 *= rn; qx *= rn; qy *= rn; qz *= rn;

    // quaternion -> rotation matrix (maps src -> tgt)
    float xx = qx * qx, yy = qy * qy, zz = qz * qz;
    float xy = qx * qy, xz = qx * qz, yz = qy * qz;
    float wxq = q0 * qx, wyq = q0 * qy, wzq = q0 * qz;
    float R00 = 1.0f - 2.0f * (yy + zz), R01 = 2.0f * (xy - wzq), R02 = 2.0f * (xz + wyq);
    float R10 = 2.0f * (xy + wzq), R11 = 1.0f - 2.0f * (xx + zz), R12 = 2.0f * (yz - wxq);
    float R20 = 2.0f * (xz - wyq), R21 = 2.0f * (yz + wxq), R22 = 1.0f - 2.0f * (xx + yy);

    // centroids and translation: t = tgt_c - R * src_c
    float cxs = sx * invD, cys = sy * invD, czs = sz * invD;
    float cxt = tx * invD, cyt = ty * invD, czt = tz * invD;
    float t0 = cxt - (R00 * cxs + R01 * cys + R02 * czs);
    float t1 = cyt - (R10 * cxs + R11 * cys + R12 * czs);
    float t2 = czt - (R20 * cxs + R21 * cys + R22 * czs);

    float* Ro = out + (size_t)b * 9;
    Ro[0] = R00; Ro[1] = R01; Ro[2] = R02;
    Ro[3] = R10; Ro[4] = R11; Ro[5] = R12;
    Ro[6] = R20; Ro[7] = R21; Ro[8] = R22;
    float* To = out + (size_t)PB * 9 + (size_t)b * 3;
    To[0] = t0; To[1] = t1; To[2] = t2;
}

extern "C" void kernel_launch(void* const* d_in, const int* in_sizes, int n_in,
                              void* d_out, int out_size) {
    const float* src = (const float*)d_in[0];
    const float* tgt = (const float*)d_in[1];
    const float* wgt = (const float*)d_in[2];
    float* out = (float*)d_out;
    wproc_reduce<<<PB / BPC, K1_THREADS>>>(src, tgt, wgt);
    wproc_solve<<<PB / K2_THREADS, K2_THREADS>>>(out);
}

// round 12
// speedup vs baseline: 1.5928x; 1.0917x over previous
#include <cuda_runtime.h>

// WeightedProcrustes: B=8192 batches, N=512 points.
// R12: K1 unchanged (75% DRAM). K2 Jacobi on MUFU fast path with the
// overflow-free tangent formula  t = 2*apq*sign(d) / (|d| + sqrt(d^2+4*apq^2))
// (R11's theta=d/apq overflowed to inf when apq->0, and inf*rsqrtf(inf)=NaN).

#define PB 8192
#define PN 512

constexpr int BPC = 4;        // batches per CTA in K1 (= warps per CTA)
constexpr int K1_THREADS = 128;
constexpr int K2_THREADS = 128;

// scratch[i][b]: statistic i of batch b (transposed for coalesced K2 reads)
__device__ float g_scratch[16][PB];

// ---------------------------------------------------------------------------
// Kernel 1: reduction only (UNCHANGED from R10)
// ---------------------------------------------------------------------------
__global__ __launch_bounds__(K1_THREADS) void wproc_reduce(
    const float* __restrict__ src, const float* __restrict__ tgt,
    const float* __restrict__ wgt)
{
    const int lane = threadIdx.x & 31;
    const int warp = threadIdx.x >> 5;
    const int b = blockIdx.x * BPC + warp;

    const float4* s4 = reinterpret_cast<const float4*>(src) + (size_t)b * (PN * 3 / 4);
    const float4* t4 = reinterpret_cast<const float4*>(tgt) + (size_t)b * (PN * 3 / 4);
    const float4* w4 = reinterpret_cast<const float4*>(wgt) + (size_t)b * (PN / 4);

    float S = 0.f, sx = 0.f, sy = 0.f, sz = 0.f, tx = 0.f, ty = 0.f, tz = 0.f;
    float M00 = 0.f, M01 = 0.f, M02 = 0.f;
    float M10 = 0.f, M11 = 0.f, M12 = 0.f;
    float M20 = 0.f, M21 = 0.f, M22 = 0.f;

    auto acc = [&](float w, float ax, float ay, float az,
                   float bx, float by, float bz) {
        w = fmaxf(w, 0.0f);  // threshold at 0.0
        S += w;
        float wx = w * ax, wy = w * ay, wz = w * az;
        sx += wx; sy += wy; sz += wz;
        tx = fmaf(w, bx, tx); ty = fmaf(w, by, ty); tz = fmaf(w, bz, tz);
        M00 = fmaf(wx, bx, M00); M01 = fmaf(wx, by, M01); M02 = fmaf(wx, bz, M02);
        M10 = fmaf(wy, bx, M10); M11 = fmaf(wy, by, M11); M12 = fmaf(wy, bz, M12);
        M20 = fmaf(wz, bx, M20); M21 = fmaf(wz, by, M21); M22 = fmaf(wz, bz, M22);
    };

    #pragma unroll
    for (int k = 0; k < 4; k++) {
        const int g = k * 32 + lane;           // group of 4 points
        float4 sa = s4[3 * g + 0];
        float4 sb = s4[3 * g + 1];
        float4 sc = s4[3 * g + 2];
        float4 ta = t4[3 * g + 0];
        float4 tb = t4[3 * g + 1];
        float4 tc = t4[3 * g + 2];
        float4 wv = w4[g];
        acc(wv.x, sa.x, sa.y, sa.z, ta.x, ta.y, ta.z);
        acc(wv.y, sa.w, sb.x, sb.y, ta.w, tb.x, tb.y);
        acc(wv.z, sb.z, sb.w, sc.x, tb.z, tb.w, tc.x);
        acc(wv.w, sc.y, sc.z, sc.w, tc.y, tc.z, tc.w);
    }

    float v[16] = {S, sx, sy, sz, tx, ty, tz,
                   M00, M01, M02, M10, M11, M12, M20, M21, M22};
    #pragma unroll
    for (int o = 16; o > 0; o >>= 1) {
        #pragma unroll
        for (int i = 0; i < 16; i++)
            v[i] += __shfl_xor_sync(0xffffffffu, v[i], o);
    }
    if (lane == 0) {
        #pragma unroll
        for (int i = 0; i < 16; i++) g_scratch[i][b] = v[i];
    }
}

// ---------------------------------------------------------------------------
// Kernel 2: one batch per thread — Horn quaternion via 4x4 Jacobi (fast-math,
// overflow-free rotation)
// ---------------------------------------------------------------------------
__global__ __launch_bounds__(K2_THREADS) void wproc_solve(float* __restrict__ out)
{
    const int b = blockIdx.x * K2_THREADS + threadIdx.x;

    const float S  = g_scratch[0][b];
    const float sx = g_scratch[1][b], sy = g_scratch[2][b], sz = g_scratch[3][b];
    const float tx = g_scratch[4][b], ty = g_scratch[5][b], tz = g_scratch[6][b];
    const float M00 = g_scratch[7][b],  M01 = g_scratch[8][b],  M02 = g_scratch[9][b];
    const float M10 = g_scratch[10][b], M11 = g_scratch[11][b], M12 = g_scratch[12][b];
    const float M20 = g_scratch[13][b], M21 = g_scratch[14][b], M22 = g_scratch[15][b];

    const float invD = __fdividef(1.0f, S + 1e-5f);
    const float kc   = (2.0f - S * invD) * invD;  // (2-W)/D

    // H = M - kc * sx * tx^T   (scale of H is irrelevant for the eigenvector)
    float H00 = fmaf(-kc * sx, tx, M00), H01 = fmaf(-kc * sx, ty, M01), H02 = fmaf(-kc * sx, tz, M02);
    float H10 = fmaf(-kc * sy, tx, M10), H11 = fmaf(-kc * sy, ty, M11), H12 = fmaf(-kc * sy, tz, M12);
    float H20 = fmaf(-kc * sz, tx, M20), H21 = fmaf(-kc * sz, ty, M21), H22 = fmaf(-kc * sz, tz, M22);

    // Horn's 4x4 symmetric matrix
    float A[4][4], V[4][4];
    A[0][0] = H00 + H11 + H22;
    A[0][1] = H12 - H21;  A[0][2] = H20 - H02;  A[0][3] = H01 - H10;
    A[1][1] = H00 - H11 - H22;
    A[1][2] = H01 + H10;  A[1][3] = H20 + H02;
    A[2][2] = -H00 + H11 - H22;
    A[2][3] = H12 + H21;
    A[3][3] = -H00 - H11 + H22;
    A[1][0] = A[0][1]; A[2][0] = A[0][2]; A[3][0] = A[0][3];
    A[2][1] = A[1][2]; A[3][1] = A[1][3]; A[3][2] = A[2][3];
    #pragma unroll
    for (int i = 0; i < 4; i++)
        #pragma unroll
        for (int j = 0; j < 4; j++)
            V[i][j] = (i == j) ? 1.0f : 0.0f;

    // Cyclic Jacobi, 5 sweeps, MUFU fast-path, overflow-free tangent:
    //   t = 2*apq*sign(d) / (|d| + sqrt(d^2 + 4*apq^2)),  d = aqq - app
    // Guard |apq| > 1e-18 keeps 4*apq^2 above FLT_MIN (no rsqrtf(0)=inf pole).
    #pragma unroll
    for (int sweep = 0; sweep < 5; sweep++) {
        #pragma unroll
        for (int pi = 0; pi < 6; pi++) {
            const int Pidx[6] = {0, 0, 0, 1, 1, 2};
            const int Qidx[6] = {1, 2, 3, 2, 3, 3};
            const int p = Pidx[pi], q = Qidx[pi];
            float apq = A[p][q];
            float c, s, t;
            if (fabsf(apq) > 1e-18f) {
                float d  = A[q][q] - A[p][p];
                float r2 = fmaf(d, d, 4.0f * apq * apq);   // >= 4e-36 > 0
                float sq = r2 * rsqrtf(r2);                // sqrt(r2), finite
                t = __fdividef(2.0f * apq * copysignf(1.0f, d),
                               fabsf(d) + sq);
                c = rsqrtf(fmaf(t, t, 1.0f));
                s = t * c;
            } else {
                c = 1.0f; s = 0.0f; t = 0.0f;
            }
            A[p][p] = fmaf(-t, apq, A[p][p]);
            A[q][q] = fmaf( t, apq, A[q][q]);
            A[p][q] = 0.0f; A[q][p] = 0.0f;
            #pragma unroll
            for (int r = 0; r < 4; r++) {
                if (r != p && r != q) {
                    float arp = A[r][p], arq = A[r][q];
                    A[r][p] = A[p][r] = fmaf(c, arp, -s * arq);
                    A[r][q] = A[q][r] = fmaf(s, arp,  c * arq);
                }
                float vrp = V[r][p], vrq = V[r][q];
                V[r][p] = fmaf(c, vrp, -s * vrq);
                V[r][q] = fmaf(s, vrp,  c * vrq);
            }
        }
    }

    // pick eigenvector of max eigenvalue
    float dm = A[0][0];
    float q0 = V[0][0], qx = V[1][0], qy = V[2][0], qz = V[3][0];
    if (A[1][1] > dm) { dm = A[1][1]; q0 = V[0][1]; qx = V[1][1]; qy = V[2][1]; qz = V[3][1]; }
    if (A[2][2] > dm) { dm = A[2][2]; q0 = V[0][2]; qx = V[1][2]; qy = V[2][2]; qz = V[3][2]; }
    if (A[3][3] > dm) { dm = A[3][3]; q0 = V[0][3]; qx = V[1][3]; qy = V[2][3]; qz = V[3][3]; }

    float rn = rsqrtf(q0 * q0 + qx * qx + qy * qy + qz * qz);
    q0 *= rn; qx *= rn; qy *= rn; qz *= rn;

    // quaternion -> rotation matrix (maps src -> tgt)
    float xx = qx * qx, yy = qy * qy, zz = qz * qz;
    float xy = qx * qy, xz = qx * qz, yz = qy * qz;
    float wxq = q0 * qx, wyq = q0 * qy, wzq = q0 * qz;
    float R00 = 1.0f - 2.0f * (yy + zz), R01 = 2.0f * (xy - wzq), R02 = 2.0f * (xz + wyq);
    float R10 = 2.0f * (xy + wzq), R11 = 1.0f - 2.0f * (xx + zz), R12 = 2.0f * (yz - wxq);
    float R20 = 2.0f * (xz - wyq), R21 = 2.0f * (yz + wxq), R22 = 1.0f - 2.0f * (xx + yy);

    // centroids and translation: t = tgt_c - R * src_c
    float cxs = sx * invD, cys = sy * invD, czs = sz * invD;
    float cxt = tx * invD, cyt = ty * invD, czt = tz * invD;
    float t0 = cxt - (R00 * cxs + R01 * cys + R02 * czs);
    float t1 = cyt - (R10 * cxs + R11 * cys + R12 * czs);
    float t2 = czt - (R20 * cxs + R21 * cys + R22 * czs);

    float* Ro = out + (size_t)b * 9;
    Ro[0] = R00; Ro[1] = R01; Ro[2] = R02;
    Ro[3] = R10; Ro[4] = R11; Ro[5] = R12;
    Ro[6] = R20; Ro[7] = R21; Ro[8] = R22;
    float* To = out + (size_t)PB * 9 + (size_t)b * 3;
    To[0] = t0; To[1] = t1; To[2] = t2;
}

extern "C" void kernel_launch(void* const* d_in, const int* in_sizes, int n_in,
                              void* d_out, int out_size) {
    const float* src = (const float*)d_in[0];
    const float* tgt = (const float*)d_in[1];
    const float* wgt = (const float*)d_in[2];
    float* out = (float*)d_out;
    wproc_reduce<<<PB / BPC, K1_THREADS>>>(src, tgt, wgt);
    wproc_solve<<<PB / K2_THREADS, K2_THREADS>>>(out);
}

// round 14
// speedup vs baseline: 1.8140x; 1.1389x over previous
#include <cuda_runtime.h>

// WeightedProcrustes: B=8192 batches, N=512 points.
// R13: K1 unchanged (72% of HBM floor). K2: branch-free Jacobi rotation
// (apq=0 gives t=0 naturally; r2 clamped so rsqrtf never sees 0) removing
// 30 BSSY/BSYNC pairs from the serial chain; sweeps 5 -> 4.

#define PB 8192
#define PN 512

constexpr int BPC = 4;        // batches per CTA in K1 (= warps per CTA)
constexpr int K1_THREADS = 128;
constexpr int K2_THREADS = 128;

// scratch[i][b]: statistic i of batch b (transposed for coalesced K2 reads)
__device__ float g_scratch[16][PB];

// ---------------------------------------------------------------------------
// Kernel 1: reduction only (UNCHANGED from R10/R12)
// ---------------------------------------------------------------------------
__global__ __launch_bounds__(K1_THREADS) void wproc_reduce(
    const float* __restrict__ src, const float* __restrict__ tgt,
    const float* __restrict__ wgt)
{
    const int lane = threadIdx.x & 31;
    const int warp = threadIdx.x >> 5;
    const int b = blockIdx.x * BPC + warp;

    const float4* s4 = reinterpret_cast<const float4*>(src) + (size_t)b * (PN * 3 / 4);
    const float4* t4 = reinterpret_cast<const float4*>(tgt) + (size_t)b * (PN * 3 / 4);
    const float4* w4 = reinterpret_cast<const float4*>(wgt) + (size_t)b * (PN / 4);

    float S = 0.f, sx = 0.f, sy = 0.f, sz = 0.f, tx = 0.f, ty = 0.f, tz = 0.f;
    float M00 = 0.f, M01 = 0.f, M02 = 0.f;
    float M10 = 0.f, M11 = 0.f, M12 = 0.f;
    float M20 = 0.f, M21 = 0.f, M22 = 0.f;

    auto acc = [&](float w, float ax, float ay, float az,
                   float bx, float by, float bz) {
        w = fmaxf(w, 0.0f);  // threshold at 0.0
        S += w;
        float wx = w * ax, wy = w * ay, wz = w * az;
        sx += wx; sy += wy; sz += wz;
        tx = fmaf(w, bx, tx); ty = fmaf(w, by, ty); tz = fmaf(w, bz, tz);
        M00 = fmaf(wx, bx, M00); M01 = fmaf(wx, by, M01); M02 = fmaf(wx, bz, M02);
        M10 = fmaf(wy, bx, M10); M11 = fmaf(wy, by, M11); M12 = fmaf(wy, bz, M12);
        M20 = fmaf(wz, bx, M20); M21 = fmaf(wz, by, M21); M22 = fmaf(wz, bz, M22);
    };

    #pragma unroll
    for (int k = 0; k < 4; k++) {
        const int g = k * 32 + lane;           // group of 4 points
        float4 sa = s4[3 * g + 0];
        float4 sb = s4[3 * g + 1];
        float4 sc = s4[3 * g + 2];
        float4 ta = t4[3 * g + 0];
        float4 tb = t4[3 * g + 1];
        float4 tc = t4[3 * g + 2];
        float4 wv = w4[g];
        acc(wv.x, sa.x, sa.y, sa.z, ta.x, ta.y, ta.z);
        acc(wv.y, sa.w, sb.x, sb.y, ta.w, tb.x, tb.y);
        acc(wv.z, sb.z, sb.w, sc.x, tb.z, tb.w, tc.x);
        acc(wv.w, sc.y, sc.z, sc.w, tc.y, tc.z, tc.w);
    }

    float v[16] = {S, sx, sy, sz, tx, ty, tz,
                   M00, M01, M02, M10, M11, M12, M20, M21, M22};
    #pragma unroll
    for (int o = 16; o > 0; o >>= 1) {
        #pragma unroll
        for (int i = 0; i < 16; i++)
            v[i] += __shfl_xor_sync(0xffffffffu, v[i], o);
    }
    if (lane == 0) {
        #pragma unroll
        for (int i = 0; i < 16; i++) g_scratch[i][b] = v[i];
    }
}

// ---------------------------------------------------------------------------
// Kernel 2: one batch per thread — Horn quaternion via 4x4 Jacobi
// (branch-free, MUFU fast-path, overflow-free rotation)
// ---------------------------------------------------------------------------
__global__ __launch_bounds__(K2_THREADS) void wproc_solve(float* __restrict__ out)
{
    const int b = blockIdx.x * K2_THREADS + threadIdx.x;

    const float S  = g_scratch[0][b];
    const float sx = g_scratch[1][b], sy = g_scratch[2][b], sz = g_scratch[3][b];
    const float tx = g_scratch[4][b], ty = g_scratch[5][b], tz = g_scratch[6][b];
    const float M00 = g_scratch[7][b],  M01 = g_scratch[8][b],  M02 = g_scratch[9][b];
    const float M10 = g_scratch[10][b], M11 = g_scratch[11][b], M12 = g_scratch[12][b];
    const float M20 = g_scratch[13][b], M21 = g_scratch[14][b], M22 = g_scratch[15][b];

    const float invD = __fdividef(1.0f, S + 1e-5f);
    const float kc   = (2.0f - S * invD) * invD;  // (2-W)/D

    // H = M - kc * sx * tx^T   (scale of H is irrelevant for the eigenvector)
    float H00 = fmaf(-kc * sx, tx, M00), H01 = fmaf(-kc * sx, ty, M01), H02 = fmaf(-kc * sx, tz, M02);
    float H10 = fmaf(-kc * sy, tx, M10), H11 = fmaf(-kc * sy, ty, M11), H12 = fmaf(-kc * sy, tz, M12);
    float H20 = fmaf(-kc * sz, tx, M20), H21 = fmaf(-kc * sz, ty, M21), H22 = fmaf(-kc * sz, tz, M22);

    // Horn's 4x4 symmetric matrix
    float A[4][4], V[4][4];
    A[0][0] = H00 + H11 + H22;
    A[0][1] = H12 - H21;  A[0][2] = H20 - H02;  A[0][3] = H01 - H10;
    A[1][1] = H00 - H11 - H22;
    A[1][2] = H01 + H10;  A[1][3] = H20 + H02;
    A[2][2] = -H00 + H11 - H22;
    A[2][3] = H12 + H21;
    A[3][3] = -H00 - H11 + H22;
    A[1][0] = A[0][1]; A[2][0] = A[0][2]; A[3][0] = A[0][3];
    A[2][1] = A[1][2]; A[3][1] = A[1][3]; A[3][2] = A[2][3];
    #pragma unroll
    for (int i = 0; i < 4; i++)
        #pragma unroll
        for (int j = 0; j < 4; j++)
            V[i][j] = (i == j) ? 1.0f : 0.0f;

    // Cyclic Jacobi, 4 sweeps, branch-free rotation:
    //   t = 2*apq*sign(d) / (|d| + sqrt(max(d^2 + 4*apq^2, 1e-30)))
    // apq == 0  =>  numerator 0  =>  t=0, c=1, s=0 (identity rotation), so no
    // guard branch is needed; the clamp only protects rsqrtf(0).
    #pragma unroll
    for (int sweep = 0; sweep < 4; sweep++) {
        #pragma unroll
        for (int pi = 0; pi < 6; pi++) {
            const int Pidx[6] = {0, 0, 0, 1, 1, 2};
            const int Qidx[6] = {1, 2, 3, 2, 3, 3};
            const int p = Pidx[pi], q = Qidx[pi];
            const float apq = A[p][q];
            const float d   = A[q][q] - A[p][p];
            float r2 = fmaf(d, d, 4.0f * apq * apq);
            r2 = fmaxf(r2, 1e-30f);
            const float sq = r2 * rsqrtf(r2);              // sqrt(r2), finite
            const float t  = __fdividef(2.0f * apq * copysignf(1.0f, d),
                                        fabsf(d) + sq);
            const float c  = rsqrtf(fmaf(t, t, 1.0f));
            const float s  = t * c;

            A[p][p] = fmaf(-t, apq, A[p][p]);
            A[q][q] = fmaf( t, apq, A[q][q]);
            A[p][q] = 0.0f; A[q][p] = 0.0f;
            #pragma unroll
            for (int r = 0; r < 4; r++) {
                if (r != p && r != q) {
                    float arp = A[r][p], arq = A[r][q];
                    A[r][p] = A[p][r] = fmaf(c, arp, -s * arq);
                    A[r][q] = A[q][r] = fmaf(s, arp,  c * arq);
                }
                float vrp = V[r][p], vrq = V[r][q];
                V[r][p] = fmaf(c, vrp, -s * vrq);
                V[r][q] = fmaf(s, vrp,  c * vrq);
            }
        }
    }

    // pick eigenvector of max eigenvalue
    float dm = A[0][0];
    float q0 = V[0][0], qx = V[1][0], qy = V[2][0], qz = V[3][0];
    if (A[1][1] > dm) { dm = A[1][1]; q0 = V[0][1]; qx = V[1][1]; qy = V[2][1]; qz = V[3][1]; }
    if (A[2][2] > dm) { dm = A[2][2]; q0 = V[0][2]; qx = V[1][2]; qy = V[2][2]; qz = V[3][2]; }
    if (A[3][3] > dm) { dm = A[3][3]; q0 = V[0][3]; qx = V[1][3]; qy = V[2][3]; qz = V[3][3]; }

    float rn = rsqrtf(q0 * q0 + qx * qx + qy * qy + qz * qz);
    q0 *= rn; qx *= rn; qy *= rn; qz *= rn;

    // quaternion -> rotation matrix (maps src -> tgt)
    float xx = qx * qx, yy = qy * qy, zz = qz * qz;
    float xy = qx * qy, xz = qx * qz, yz = qy * qz;
    float wxq = q0 * qx, wyq = q0 * qy, wzq = q0 * qz;
    float R00 = 1.0f - 2.0f * (yy + zz), R01 = 2.0f * (xy - wzq), R02 = 2.0f * (xz + wyq);
    float R10 = 2.0f * (xy + wzq), R11 = 1.0f - 2.0f * (xx + zz), R12 = 2.0f * (yz - wxq);
    float R20 = 2.0f * (xz - wyq), R21 = 2.0f * (yz + wxq), R22 = 1.0f - 2.0f * (xx + yy);

    // centroids and translation: t = tgt_c - R * src_c
    float cxs = sx * invD, cys = sy * invD, czs = sz * invD;
    float cxt = tx * invD, cyt = ty * invD, czt = tz * invD;
    float t0 = cxt - (R00 * cxs + R01 * cys + R02 * czs);
    float t1 = cyt - (R10 * cxs + R11 * cys + R12 * czs);
    float t2 = czt - (R20 * cxs + R21 * cys + R22 * czs);

    float* Ro = out + (size_t)b * 9;
    Ro[0] = R00; Ro[1] = R01; Ro[2] = R02;
    Ro[3] = R10; Ro[4] = R11; Ro[5] = R12;
    Ro[6] = R20; Ro[7] = R21; Ro[8] = R22;
    float* To = out + (size_t)PB * 9 + (size_t)b * 3;
    To[0] = t0; To[1] = t1; To[2] = t2;
}

extern "C" void kernel_launch(void* const* d_in, const int* in_sizes, int n_in,
                              void* d_out, int out_size) {
    const float* src = (const float*)d_in[0];
    const float* tgt = (const float*)d_in[1];
    const float* wgt = (const float*)d_in[2];
    float* out = (float*)d_out;
    wproc_reduce<<<PB / BPC, K1_THREADS>>>(src, tgt, wgt);
    wproc_solve<<<PB / K2_THREADS, K2_THREADS>>>(out);
}